// round 3
// baseline (speedup 1.0000x reference)
#include <cuda_runtime.h>
#include <cstdint>

// DiscriminationLoss: B=16, C=4, H=W=640, labels in [0,16]
// loss = sum_b [ (sum over valid pairs i<j, i>=1 of log1p((3 - sqrt(m_i+m_j))^2)) / (nk*(nk-1)) ]
// m_k = SS_k / card_k^2, SS_k = per-segment sum of per-pixel squared channel norms.
//
// Design: single-pass HBM-bound segment reduction, 2 launches.
//  - float4/int4 vectorized loads, 5x 128B lines in flight per thread-iter.
//  - Per-thread private bins in smem, layout [bin][tid] (stride 256 -> bank
//    = tid%32 -> conflict-free plain LDS/STS; no shared atomics despite
//    random labels).
//  - Each block writes its partials to a private scratch slot (always fully
//    overwritten -> no zero-pass needed, graph-replay deterministic).
//  - Finalize: 1 block, warp-per-batch reduction of 37 partials + 120-pair
//    log1p epilogue.

#define BATCH 16
#define CHAN 4
#define PIX (640 * 640)
#define NK 17            // labels 0..16
#define SIGMA_DIS 3.0f
#define GX 37            // blocks per batch (37*16 = 592 = 4/SM on 148 SMs)

// Scratch (__device__ globals; no allocations allowed). Every element is
// unconditionally written by segment_reduce each replay -> no init required.
__device__ float g_part_ss [BATCH][GX][NK];
__device__ float g_part_cnt[BATCH][GX][NK];
__device__ int   g_part_max[BATCH][GX];

// ---------------------------------------------------------------------------
// Kernel 1: segment reduction.
// ---------------------------------------------------------------------------
__global__ __launch_bounds__(256, 4)
void segment_reduce_kernel(const float* __restrict__ pred,
                           const int*  __restrict__ labels) {
    __shared__ float s_ss [NK][256];
    __shared__ float s_cnt[NK][256];
    __shared__ int   s_max;

    const int tid = threadIdx.x;
    const int bx  = blockIdx.x;
    const int b   = blockIdx.y;

    #pragma unroll
    for (int k = 0; k < NK; k++) {
        s_ss [k][tid] = 0.0f;
        s_cnt[k][tid] = 0.0f;
    }
    if (tid == 0) s_max = 0;
    __syncthreads();

    const float* p0 = pred + (size_t)b * CHAN * PIX;
    const int*   l0 = labels + (size_t)b * PIX;

    const float4* c0 = (const float4*)(p0);
    const float4* c1 = (const float4*)(p0 + PIX);
    const float4* c2 = (const float4*)(p0 + 2 * PIX);
    const float4* c3 = (const float4*)(p0 + 3 * PIX);
    const int4*   lv4 = (const int4*)(l0);

    int maxl = 0;
    const int n4     = PIX / 4;                  // 102400
    const int stride = GX * 256;                 // float4-granularity stride

    for (int i = bx * 256 + tid; i < n4; i += stride) {
        float4 x0 = c0[i];
        float4 x1 = c1[i];
        float4 x2 = c2[i];
        float4 x3 = c3[i];
        int4   lv = lv4[i];

        float sq0 = x0.x * x0.x + x1.x * x1.x + x2.x * x2.x + x3.x * x3.x;
        float sq1 = x0.y * x0.y + x1.y * x1.y + x2.y * x2.y + x3.y * x3.y;
        float sq2 = x0.z * x0.z + x1.z * x1.z + x2.z * x2.z + x3.z * x3.z;
        float sq3 = x0.w * x0.w + x1.w * x1.w + x2.w * x2.w + x3.w * x3.w;

        // labels are in [0,16] by construction; clamp defensively (cheap IMNMX)
        int la = min(max(lv.x, 0), NK - 1);
        int lb = min(max(lv.y, 0), NK - 1);
        int lc = min(max(lv.z, 0), NK - 1);
        int ld = min(max(lv.w, 0), NK - 1);

        // private bins: same-thread sequential RMW, no races, no bank conflicts
        s_ss [la][tid] += sq0;  s_cnt[la][tid] += 1.0f;
        s_ss [lb][tid] += sq1;  s_cnt[lb][tid] += 1.0f;
        s_ss [lc][tid] += sq2;  s_cnt[lc][tid] += 1.0f;
        s_ss [ld][tid] += sq3;  s_cnt[ld][tid] += 1.0f;

        maxl = max(maxl, max(max(la, lb), max(lc, ld)));
    }

    // warp-reduce max, then block
    #pragma unroll
    for (int o = 16; o > 0; o >>= 1)
        maxl = max(maxl, __shfl_xor_sync(0xFFFFFFFFu, maxl, o));
    if ((tid & 31) == 0) atomicMax(&s_max, maxl);

    __syncthreads();

    // block tree-reduce the 256 private columns per bin
    for (int s = 128; s >= 1; s >>= 1) {
        if (tid < s) {
            #pragma unroll
            for (int k = 0; k < NK; k++) {
                s_ss [k][tid] += s_ss [k][tid + s];
                s_cnt[k][tid] += s_cnt[k][tid + s];
            }
        }
        __syncthreads();
    }

    // plain stores to this block's private scratch slot (no atomics)
    if (tid < NK) {
        g_part_ss [b][bx][tid] = s_ss [tid][0];
        g_part_cnt[b][bx][tid] = s_cnt[tid][0];
    }
    if (tid == 0) g_part_max[b][bx] = s_max;
}

// ---------------------------------------------------------------------------
// Kernel 2: finalize — reduce block partials, pairwise term, scalar loss.
// One block, 16 warps; warp w handles batch w.
// ---------------------------------------------------------------------------
__global__ __launch_bounds__(512, 1)
void finalize_kernel(float* __restrict__ out) {
    __shared__ float partial[BATCH];

    const int lane = threadIdx.x & 31;
    const int b    = threadIdx.x >> 5;   // warp id = batch id (16 warps)

    float ss[NK], cnt[NK];
    #pragma unroll
    for (int k = 0; k < NK; k++) { ss[k] = 0.0f; cnt[k] = 0.0f; }
    int maxl = 0;

    // lanes stride over the GX=37 block partials
    for (int bx = lane; bx < GX; bx += 32) {
        #pragma unroll
        for (int k = 0; k < NK; k++) {
            ss[k]  += g_part_ss [b][bx][k];
            cnt[k] += g_part_cnt[b][bx][k];
        }
        maxl = max(maxl, g_part_max[b][bx]);
    }

    // warp reduce all bins + max
    #pragma unroll
    for (int o = 16; o > 0; o >>= 1) {
        #pragma unroll
        for (int k = 0; k < NK; k++) {
            ss[k]  += __shfl_xor_sync(0xFFFFFFFFu, ss[k],  o);
            cnt[k] += __shfl_xor_sync(0xFFFFFFFFu, cnt[k], o);
        }
        maxl = max(maxl, __shfl_xor_sync(0xFFFFFFFFu, maxl, o));
    }

    if (lane == 0) {
        float m[NK];
        #pragma unroll
        for (int k = 0; k < NK; k++)
            m[k] = (cnt[k] > 0.0f) ? ss[k] / (cnt[k] * cnt[k]) : 0.0f;

        float ps = 0.0f;
        #pragma unroll
        for (int i = 1; i < NK; i++) {
            if (cnt[i] <= 0.0f) continue;
            #pragma unroll
            for (int j = i + 1; j < NK; j++) {
                if (cnt[j] <= 0.0f) continue;
                float d = sqrtf(m[i] + m[j]);
                float t = SIGMA_DIS - d;
                ps += log1pf(t * t);
            }
        }
        float loss = 0.0f;
        if (maxl > 1) {
            float denom = (float)(maxl * (maxl - 1));
            loss = ps / fmaxf(denom, 1.0f);
        }
        partial[b] = loss;
    }
    __syncthreads();

    if (threadIdx.x == 0) {
        float s = 0.0f;
        #pragma unroll
        for (int k = 0; k < BATCH; k++) s += partial[k];
        out[0] = s;
    }
}

// ---------------------------------------------------------------------------
extern "C" void kernel_launch(void* const* d_in, const int* in_sizes, int n_in,
                              void* d_out, int out_size) {
    const float* pred   = (const float*)d_in[0];   // (16,4,640,640) f32
    const int*   labels = (const int*)d_in[1];     // (16,640,640) i32
    float*       out    = (float*)d_out;

    dim3 grid(GX, BATCH);   // 592 blocks = 4/SM on 148 SMs, one wave
    segment_reduce_kernel<<<grid, 256>>>(pred, labels);

    finalize_kernel<<<1, 512>>>(out);
}

// round 10
// speedup vs baseline: 1.4054x; 1.4054x over previous
#include <cuda_runtime.h>
#include <cstdint>

// DiscriminationLoss: B=16, C=4, H=W=640, labels in [0,16]
// loss = sum_b [ (sum over valid pairs i<j, i>=1 of log1p((3 - sqrt(m_i+m_j))^2)) / (nk*(nk-1)) ]
// m_k = SS_k / card_k^2.
//
// vs R3 baseline (58.2us; finalize alone 40.3us = 120 pair terms serial on
// lane 0):
//  - finalize: butterfly reduce leaves totals in ALL lanes; pair loop split
//    4 pairs/lane via a __constant__ (i,j) lookup table.
//  - mainloop: ss+cnt fused into float2 smem bins (LDS.64 RMW, 4 serialized
//    RMW chains per pixel-quad instead of 8).

#define BATCH 16
#define CHAN 4
#define PIX (640 * 640)
#define NK 17            // labels 0..16
#define SIGMA_DIS 3.0f
#define GX 37            // blocks per batch (37*16 = 592 = 4/SM on 148 SMs)
#define NPAIR 120        // C(16,2) pairs with 1 <= i < j <= 16

// Packed pair table: entry t = (i << 5) | j, lexicographic (i,j), i<j.
__constant__ unsigned short c_pair[NPAIR] = {
    // i = 1: j = 2..16
    34,35,36,37,38,39,40,41,42,43,44,45,46,47,48,
    // i = 2: j = 3..16
    67,68,69,70,71,72,73,74,75,76,77,78,79,80,
    // i = 3
    100,101,102,103,104,105,106,107,108,109,110,111,112,
    // i = 4
    133,134,135,136,137,138,139,140,141,142,143,144,
    // i = 5
    166,167,168,169,170,171,172,173,174,175,176,
    // i = 6
    199,200,201,202,203,204,205,206,207,208,
    // i = 7
    232,233,234,235,236,237,238,239,240,
    // i = 8
    265,266,267,268,269,270,271,272,
    // i = 9
    298,299,300,301,302,303,304,
    // i = 10
    331,332,333,334,335,336,
    // i = 11
    364,365,366,367,368,
    // i = 12
    397,398,399,400,
    // i = 13
    430,431,432,
    // i = 14
    463,464,
    // i = 15
    496
};

// Scratch (__device__ globals). Every element unconditionally overwritten
// each replay -> no init pass needed, graph-replay deterministic.
__device__ float2 g_part[BATCH][GX][NK];   // {ss, cnt}
__device__ int    g_part_max[BATCH][GX];

// ---------------------------------------------------------------------------
// Kernel 1: segment reduction (HBM-bound streaming pass).
// ---------------------------------------------------------------------------
__global__ __launch_bounds__(256, 4)
void segment_reduce_kernel(const float* __restrict__ pred,
                           const int*  __restrict__ labels) {
    __shared__ float2 s_bin[NK][256];   // 34.8 KB; [bin][tid]: bank = tid%32,
                                        // LDS.64 two-phase, conflict-free
    __shared__ int s_max;

    const int tid = threadIdx.x;
    const int bx  = blockIdx.x;
    const int b   = blockIdx.y;

    #pragma unroll
    for (int k = 0; k < NK; k++) s_bin[k][tid] = make_float2(0.0f, 0.0f);
    if (tid == 0) s_max = 0;
    __syncthreads();

    const float* p0 = pred + (size_t)b * CHAN * PIX;
    const int*   l0 = labels + (size_t)b * PIX;

    const float4* c0 = (const float4*)(p0);
    const float4* c1 = (const float4*)(p0 + PIX);
    const float4* c2 = (const float4*)(p0 + 2 * PIX);
    const float4* c3 = (const float4*)(p0 + 3 * PIX);
    const int4*   lv4 = (const int4*)(l0);

    int maxl = 0;
    const int n4     = PIX / 4;          // 102400
    const int stride = GX * 256;

    for (int i = bx * 256 + tid; i < n4; i += stride) {
        float4 x0 = c0[i];
        float4 x1 = c1[i];
        float4 x2 = c2[i];
        float4 x3 = c3[i];
        int4   lv = lv4[i];

        float sq0 = x0.x * x0.x + x1.x * x1.x + x2.x * x2.x + x3.x * x3.x;
        float sq1 = x0.y * x0.y + x1.y * x1.y + x2.y * x2.y + x3.y * x3.y;
        float sq2 = x0.z * x0.z + x1.z * x1.z + x2.z * x2.z + x3.z * x3.z;
        float sq3 = x0.w * x0.w + x1.w * x1.w + x2.w * x2.w + x3.w * x3.w;

        int la = min(max(lv.x, 0), NK - 1);
        int lb = min(max(lv.y, 0), NK - 1);
        int lc = min(max(lv.z, 0), NK - 1);
        int ld = min(max(lv.w, 0), NK - 1);

        // per-thread private bins: sequential RMW, no races, no conflicts
        float2 v;
        v = s_bin[la][tid]; v.x += sq0; v.y += 1.0f; s_bin[la][tid] = v;
        v = s_bin[lb][tid]; v.x += sq1; v.y += 1.0f; s_bin[lb][tid] = v;
        v = s_bin[lc][tid]; v.x += sq2; v.y += 1.0f; s_bin[lc][tid] = v;
        v = s_bin[ld][tid]; v.x += sq3; v.y += 1.0f; s_bin[ld][tid] = v;

        maxl = max(maxl, max(max(la, lb), max(lc, ld)));
    }

    #pragma unroll
    for (int o = 16; o > 0; o >>= 1)
        maxl = max(maxl, __shfl_xor_sync(0xFFFFFFFFu, maxl, o));
    if ((tid & 31) == 0) atomicMax(&s_max, maxl);

    __syncthreads();

    // block tree-reduce the 256 private columns per bin
    for (int s = 128; s >= 1; s >>= 1) {
        if (tid < s) {
            #pragma unroll
            for (int k = 0; k < NK; k++) {
                float2 a = s_bin[k][tid];
                float2 c = s_bin[k][tid + s];
                a.x += c.x; a.y += c.y;
                s_bin[k][tid] = a;
            }
        }
        __syncthreads();
    }

    // plain stores to this block's private scratch slot (no atomics)
    if (tid < NK) g_part[b][bx][tid] = s_bin[tid][0];
    if (tid == 0) g_part_max[b][bx] = s_max;
}

// ---------------------------------------------------------------------------
// Kernel 2: finalize. 1 block, 16 warps; warp w = batch w.
// ---------------------------------------------------------------------------
__global__ __launch_bounds__(512, 1)
void finalize_kernel(float* __restrict__ out) {
    __shared__ float s_loss[BATCH];

    const int lane = threadIdx.x & 31;
    const int b    = threadIdx.x >> 5;

    float ss[NK], cnt[NK];
    #pragma unroll
    for (int k = 0; k < NK; k++) { ss[k] = 0.0f; cnt[k] = 0.0f; }
    int maxl = 0;

    for (int bx = lane; bx < GX; bx += 32) {
        #pragma unroll
        for (int k = 0; k < NK; k++) {
            float2 v = g_part[b][bx][k];
            ss[k]  += v.x;
            cnt[k] += v.y;
        }
        maxl = max(maxl, g_part_max[b][bx]);
    }

    // full butterfly: every lane ends with the batch totals
    #pragma unroll
    for (int o = 16; o > 0; o >>= 1) {
        #pragma unroll
        for (int k = 0; k < NK; k++) {
            ss[k]  += __shfl_xor_sync(0xFFFFFFFFu, ss[k],  o);
            cnt[k] += __shfl_xor_sync(0xFFFFFFFFu, cnt[k], o);
        }
        maxl = max(maxl, __shfl_xor_sync(0xFFFFFFFFu, maxl, o));
    }

    float m[NK];
    #pragma unroll
    for (int k = 0; k < NK; k++)
        m[k] = (cnt[k] > 0.0f) ? ss[k] / (cnt[k] * cnt[k]) : 0.0f;

    // pair terms split across lanes: lane p takes t = p, p+32, p+64, p+96.
    // (i,j) comes from the constant table -> branch-free, un-mis-derivable.
    float ps = 0.0f;
    #pragma unroll
    for (int t = lane; t < NPAIR; t += 32) {
        int pk = (int)c_pair[t];
        int i = pk >> 5;
        int j = pk & 31;
        if (cnt[i] > 0.0f && cnt[j] > 0.0f) {
            float d = sqrtf(m[i] + m[j]);
            float u = SIGMA_DIS - d;
            ps += log1pf(u * u);
        }
    }
    #pragma unroll
    for (int o = 16; o > 0; o >>= 1)
        ps += __shfl_xor_sync(0xFFFFFFFFu, ps, o);

    if (lane == 0) {
        float loss = 0.0f;
        if (maxl > 1) {
            float denom = (float)(maxl * (maxl - 1));
            loss = ps / fmaxf(denom, 1.0f);
        }
        s_loss[b] = loss;
    }
    __syncthreads();

    if (threadIdx.x == 0) {
        float s = 0.0f;
        #pragma unroll
        for (int k = 0; k < BATCH; k++) s += s_loss[k];
        out[0] = s;
    }
}

// ---------------------------------------------------------------------------
extern "C" void kernel_launch(void* const* d_in, const int* in_sizes, int n_in,
                              void* d_out, int out_size) {
    const float* pred   = (const float*)d_in[0];   // (16,4,640,640) f32
    const int*   labels = (const int*)d_in[1];     // (16,640,640) i32
    float*       out    = (float*)d_out;

    dim3 grid(GX, BATCH);   // 592 blocks = 4/SM on 148 SMs, one wave
    segment_reduce_kernel<<<grid, 256>>>(pred, labels);

    finalize_kernel<<<1, 512>>>(out);
}